// round 14
// baseline (speedup 1.0000x reference)
#include <cuda_runtime.h>
#include <math.h>
#include <stdint.h>

// ---------------------------------------------------------------------------
// GRU: T=512, B=1024, H=128.  out = h_T @ w_out^T + b_out
//
// FUSED single kernel: 128 CTAs x 384 threads.
//   threads 0..255  = CONSUMER (R11 split-K-2 recurrence, w_hh in smem)
//   threads 256..383 = PRODUCER (computes xg[t] = x[t]@w_ih^T + b_ih for this
//                      CTA's 8 batch rows, streaming w_ih from L2 via LDG over
//                      a pre-transposed copy; writes xg to global; signals a
//                      monotonic smem counter with release semantics)
// Producer fma (3072 cyc/SMSP/step) fills the consumer's stall gap -> the old
// 1.1 ms phase-1 kernel disappears. No cross-CTA sync; producers free-run.
// ---------------------------------------------------------------------------

typedef unsigned long long u64;

static __device__ __forceinline__ u64 pack2(float lo, float hi) {
    u64 r; asm("mov.b64 %0, {%1, %2};" : "=l"(r) : "f"(lo), "f"(hi)); return r;
}
static __device__ __forceinline__ void unpack2(u64 v, float& lo, float& hi) {
    asm("mov.b64 {%0, %1}, %2;" : "=f"(lo), "=f"(hi) : "l"(v));
}
static __device__ __forceinline__ u64 ffma2(u64 a, u64 b, u64 c) {
    u64 d; asm("fma.rn.f32x2 %0, %1, %2, %3;" : "=l"(d) : "l"(a), "l"(b), "l"(c)); return d;
}
static __device__ __forceinline__ void lds_v2u64(u64& a, u64& b, uint32_t addr) {
    asm volatile("ld.shared.v2.u64 {%0, %1}, [%2];" : "=l"(a), "=l"(b) : "r"(addr));
}
static __device__ __forceinline__ void ldg_v2u64(u64& a, u64& b, const void* p) {
    asm volatile("ld.global.nc.v2.u64 {%0, %1}, [%2];" : "=l"(a), "=l"(b) : "l"(p));
}
static __device__ __forceinline__ uint32_t smem_u32(const void* p) {
    uint32_t a;
    asm("{ .reg .u64 t; cvta.to.shared.u64 t, %1; cvt.u32.u64 %0, t; }" : "=r"(a) : "l"(p));
    return a;
}
static __device__ __forceinline__ void cp16(uint32_t dst, const void* src) {
    asm volatile("cp.async.cg.shared.global [%0], [%1], 16;" :: "r"(dst), "l"(src));
}
static __device__ __forceinline__ void cp_commit() { asm volatile("cp.async.commit_group;"); }
static __device__ __forceinline__ void cp_wait1()  { asm volatile("cp.async.wait_group 1;"); }
static __device__ __forceinline__ float sigf(float x) {
    return __fdividef(1.0f, 1.0f + __expf(-x));
}
static __device__ __forceinline__ float tanhf_fast(float x) {
    float ax = fabsf(x);
    float e  = __expf(-2.0f * ax);
    float t  = __fdividef(1.0f - e, 1.0f + e);
    return copysignf(t, x);
}

constexpr int H  = 128;
constexpr int G  = 384;    // 3*H
constexpr int TT = 512;
constexpr int BB = 1024;

// xg scratch [T*B][3H] (~805 MB) and transposed w_ih [kk][g] (float4)
__device__ float  g_xg[(size_t)TT * BB * G];
__device__ float4 g_wt[32 * G];

constexpr int WS_BYTES = 32 * G * 16;   // 196608: w_hh as [kk][g] float4
constexpr int RP       = 528;           // row pitch bytes (132 floats)
constexpr int HSB      = 8 * RP;        // 4224: one h (or x) buffer
constexpr int PXSIDE   = 4 * 3 * 128 * 4;   // 6144

constexpr int OFF_HS   = WS_BYTES;               // 196608  (2 x 4224)
constexpr int OFF_PX   = OFF_HS + 2 * HSB;       // 205056  (2 x 6144)
constexpr int OFF_RED  = OFF_PX + 2 * PXSIDE;    // 217344  (4096)
constexpr int OFF_XR   = OFF_RED + 8 * H * 4;    // 221440  (2 x 4224)
constexpr int OFF_FLAG = OFF_XR + 2 * HSB;       // 229888
constexpr int SMEMF    = OFF_FLAG + 64;          // 229952  (< 232448)

constexpr int THRF = 384;

// ---------------------------------------------------------------------------
// tiny pre-kernel: transpose w_ih into [kk][g] float4 layout in global
// ---------------------------------------------------------------------------
__global__ void transpose_wih(const float* __restrict__ w_ih) {
    int i = blockIdx.x * blockDim.x + threadIdx.x;   // 0..12287
    if (i < G * 32) {
        int g = i >> 5, kk = i & 31;
        g_wt[kk * G + g] = ((const float4*)w_ih)[g * 32 + kk];
    }
}

// ---------------------------------------------------------------------------
// fused kernel
// ---------------------------------------------------------------------------
__global__ void __launch_bounds__(THRF, 1)
fused_gru(const float* __restrict__ input,
          const float* __restrict__ initial_h,
          const float* __restrict__ w_hh,
          const float* __restrict__ b_ih,
          const float* __restrict__ b_hh,
          const float* __restrict__ w_out,
          const float* __restrict__ b_out,
          float* __restrict__ out) {
    extern __shared__ char smem[];
    float4* ws4 = (float4*)smem;
    float*  hsf = (float*)(smem + OFF_HS);
    float*  pxf = (float*)(smem + OFF_PX);
    float*  red = (float*)(smem + OFF_RED);
    const uint32_t ws_a   = smem_u32(smem);
    const uint32_t hs_a   = ws_a + OFF_HS;
    const uint32_t xr_a   = ws_a + OFF_XR;
    const uint32_t flag_a = ws_a + OFF_FLAG;

    const int tid = threadIdx.x;
    const int b0  = blockIdx.x * 8;

    // ---- shared init (all 384 threads) ----
    const float4* w4 = (const float4*)w_hh;
    for (int i = tid; i < G * 32; i += THRF) {
        int g = i >> 5, kk = i & 31;
        ws4[kk * G + g] = w4[g * 32 + kk];
    }
    if (tid == 256) {
        asm volatile("st.shared.u32 [%0], %1;" :: "r"(flag_a), "r"(0u));
    }

    if (tid >= 256) {
        // producer: pre-stage x[0], x[1] via cp.async
        const int pu = tid - 256;
        const int i0 = pu, i1 = pu + 128;
        #pragma unroll
        for (int tt = 0; tt < 2; tt++) {
            const float* s0 = input + (((size_t)tt * BB + b0 + (i0 >> 5)) * H + (i0 & 31) * 4);
            const float* s1 = input + (((size_t)tt * BB + b0 + (i1 >> 5)) * H + (i1 & 31) * 4);
            cp16(xr_a + tt * HSB + (i0 >> 5) * RP + (i0 & 31) * 16, s0);
            cp16(xr_a + tt * HSB + (i1 >> 5) * RP + (i1 & 31) * 16, s1);
            cp_commit();
        }
    }

    if (tid < 256) {
        // =================== CONSUMER (R11 recurrence) ===================
        const int u  = tid & 127;
        const int kh = tid >> 7;
        const int r0 = kh * 4;
        const int ro = 4 - r0;

        const float br = b_hh[u], bz = b_hh[u + 128], bn = b_hh[u + 256];

        float hreg[4];
        #pragma unroll
        for (int i = 0; i < 4; i++) {
            hreg[i] = initial_h[(size_t)(b0 + r0 + i) * H + u];
            hsf[(r0 + i) * 132 + u] = hreg[i];
        }
        __syncthreads();   // weights + h staged (full CTA)

        // wait for xg[0], then prefetch it
        {
            uint32_t fv;
            do { asm volatile("ld.acquire.cta.shared.u32 %0, [%1];" : "=r"(fv) : "r"(flag_a)); }
            while ((int)fv < 1);
        }
        float cxR[4], cxZ[4], cxN[4];
        {
            const float* xg0 = g_xg + ((size_t)b0 + r0) * G + u;
            #pragma unroll
            for (int i = 0; i < 4; i++) {
                cxR[i] = xg0[(size_t)i * G];
                cxZ[i] = xg0[(size_t)i * G + 128];
                cxN[i] = xg0[(size_t)i * G + 256];
            }
        }

        const uint32_t wb  = ws_a + u * 16 + kh * 16 * (G * 16);
        float* pxw = pxf + kh * (4 * 3 * 128) + u;
        float* pxr = pxf + (1 - kh) * (4 * 3 * 128) + u;

        int p = 0;
        for (int t = 0; t < TT; t++) {
            // wait until xg[t+1] is published, then prefetch it
            {
                int need = (t + 2 < TT) ? (t + 2) : TT;
                uint32_t fv;
                do { asm volatile("ld.acquire.cta.shared.u32 %0, [%1];" : "=r"(fv) : "r"(flag_a)); }
                while ((int)fv < need);
            }
            float nxR[4], nxZ[4], nxN[4];
            {
                int tn = (t + 1 < TT) ? (t + 1) : t;
                const float* xgn = g_xg + ((size_t)tn * BB + b0 + r0) * G + u;
                #pragma unroll
                for (int i = 0; i < 4; i++) {
                    nxR[i] = xgn[(size_t)i * G];
                    nxZ[i] = xgn[(size_t)i * G + 128];
                    nxN[i] = xgn[(size_t)i * G + 256];
                }
            }

            // accumulators: [0..3] own rows (x folded), [4..7] other rows
            u64 aR[8], aZ[8], aN[8];
            #pragma unroll
            for (int i = 0; i < 4; i++) {
                aR[i] = pack2(cxR[i] + br, 0.f);
                aZ[i] = pack2(cxZ[i] + bz, 0.f);
                aN[i] = pack2(bn, 0.f);
                aR[4 + i] = 0; aZ[4 + i] = 0; aN[4 + i] = 0;
            }

            const uint32_t hb_own = hs_a + p * HSB + r0 * RP + kh * 256;
            const uint32_t hb_oth = hs_a + p * HSB + ro * RP + kh * 256;

            #pragma unroll 2
            for (int kk = 0; kk < 16; kk++) {
                u64 wr0, wr1, wz0, wz1, wn0, wn1;
                const uint32_t wo = wb + kk * (G * 16);
                lds_v2u64(wr0, wr1, wo);
                lds_v2u64(wz0, wz1, wo + 128 * 16);
                lds_v2u64(wn0, wn1, wo + 256 * 16);
                #pragma unroll
                for (int i = 0; i < 4; i++) {
                    u64 x0, x1;
                    lds_v2u64(x0, x1, hb_own + i * RP + kk * 16);
                    aR[i] = ffma2(x0, wr0, aR[i]); aR[i] = ffma2(x1, wr1, aR[i]);
                    aZ[i] = ffma2(x0, wz0, aZ[i]); aZ[i] = ffma2(x1, wz1, aZ[i]);
                    aN[i] = ffma2(x0, wn0, aN[i]); aN[i] = ffma2(x1, wn1, aN[i]);
                }
                #pragma unroll
                for (int i = 0; i < 4; i++) {
                    u64 x0, x1;
                    lds_v2u64(x0, x1, hb_oth + i * RP + kk * 16);
                    aR[4+i] = ffma2(x0, wr0, aR[4+i]); aR[4+i] = ffma2(x1, wr1, aR[4+i]);
                    aZ[4+i] = ffma2(x0, wz0, aZ[4+i]); aZ[4+i] = ffma2(x1, wz1, aZ[4+i]);
                    aN[4+i] = ffma2(x0, wn0, aN[4+i]); aN[4+i] = ffma2(x1, wn1, aN[4+i]);
                }
            }

            // fold own sums; export other-rows partials
            float sR[4], sZ[4], sN[4];
            #pragma unroll
            for (int i = 0; i < 4; i++) {
                float l, h2;
                unpack2(aR[i], l, h2); sR[i] = l + h2;
                unpack2(aZ[i], l, h2); sZ[i] = l + h2;
                unpack2(aN[i], l, h2); sN[i] = l + h2;
                unpack2(aR[4+i], l, h2); pxw[i * 384 + 0  ] = l + h2;
                unpack2(aZ[4+i], l, h2); pxw[i * 384 + 128] = l + h2;
                unpack2(aN[4+i], l, h2); pxw[i * 384 + 256] = l + h2;
            }
            asm volatile("bar.sync 1, 256;");   // partials exchanged; hs[p] reads done

            float* hw = hsf + (p ^ 1) * (HSB / 4) + r0 * 132 + u;
            #pragma unroll
            for (int i = 0; i < 4; i++) {
                float rg = sigf(sR[i] + pxr[i * 384 + 0]);
                float zg = sigf(sZ[i] + pxr[i * 384 + 128]);
                float ng = tanhf_fast(cxN[i] + rg * (sN[i] + pxr[i * 384 + 256]));
                hreg[i] = (1.0f - zg) * ng + zg * hreg[i];
                hw[i * 132] = hreg[i];
                cxR[i] = nxR[i]; cxZ[i] = nxZ[i]; cxN[i] = nxN[i];
            }
            asm volatile("bar.sync 1, 256;");   // new h visible
            p ^= 1;
        }

        // projection: out[b] = sum_u h[b][u]*w_out[u] + b_out
        const float wo = w_out[u];
        #pragma unroll
        for (int i = 0; i < 4; i++) red[(r0 + i) * H + u] = hreg[i] * wo;
        asm volatile("bar.sync 1, 256;");
        for (int st = 64; st > 0; st >>= 1) {
            if (u < st) {
                #pragma unroll
                for (int i = 0; i < 4; i++)
                    red[(r0 + i) * H + u] += red[(r0 + i) * H + u + st];
            }
            asm volatile("bar.sync 1, 256;");
        }
        if (tid < 8) out[b0 + tid] = red[tid * H] + b_out[0];

    } else {
        // =================== PRODUCER (input GEMM) ===================
        const int pu = tid - 256;                // 0..127
        const int i0 = pu, i1 = pu + 128;
        const float bir = b_ih[pu], biz = b_ih[pu + 128], bin = b_ih[pu + 256];

        __syncthreads();   // matches consumer's full-CTA barrier

        for (int t = 0; t < TT; t++) {
            cp_wait1();                              // x[t] staged
            asm volatile("bar.sync 2, 128;");

            const uint32_t xb = xr_a + (t & 1) * HSB;

            u64 aR[8], aZ[8], aN[8];
            #pragma unroll
            for (int r = 0; r < 8; r++) {
                aR[r] = pack2(bir, 0.f); aZ[r] = pack2(biz, 0.f); aN[r] = pack2(bin, 0.f);
            }

            #pragma unroll 4
            for (int kk = 0; kk < 32; kk++) {
                u64 wr0, wr1, wz0, wz1, wn0, wn1;
                const float4* wp = g_wt + kk * G;
                ldg_v2u64(wr0, wr1, wp + pu);            // coalesced 512B, L2-hot
                ldg_v2u64(wz0, wz1, wp + pu + 128);
                ldg_v2u64(wn0, wn1, wp + pu + 256);
                #pragma unroll
                for (int row = 0; row < 8; row++) {
                    u64 x0, x1;
                    lds_v2u64(x0, x1, xb + row * RP + kk * 16);   // broadcast
                    aR[row] = ffma2(x0, wr0, aR[row]); aR[row] = ffma2(x1, wr1, aR[row]);
                    aZ[row] = ffma2(x0, wz0, aZ[row]); aZ[row] = ffma2(x1, wz1, aZ[row]);
                    aN[row] = ffma2(x0, wn0, aN[row]); aN[row] = ffma2(x1, wn1, aN[row]);
                }
            }

            float* outp = g_xg + ((size_t)t * BB + b0) * G + pu;
            #pragma unroll
            for (int row = 0; row < 8; row++) {
                float l, h2;
                unpack2(aR[row], l, h2); outp[(size_t)row * G]       = l + h2;
                unpack2(aZ[row], l, h2); outp[(size_t)row * G + 128] = l + h2;
                unpack2(aN[row], l, h2); outp[(size_t)row * G + 256] = l + h2;
            }

            __threadfence_block();                   // STGs visible CTA-wide
            asm volatile("bar.sync 2, 128;");        // all x[t] reads + STGs done

            int tn = t + 2;
            if (tn < TT) {                           // refill buffer (t&1) with x[t+2]
                const float* s0 = input + (((size_t)tn * BB + b0 + (i0 >> 5)) * H + (i0 & 31) * 4);
                const float* s1 = input + (((size_t)tn * BB + b0 + (i1 >> 5)) * H + (i1 & 31) * 4);
                cp16(xr_a + (t & 1) * HSB + (i0 >> 5) * RP + (i0 & 31) * 16, s0);
                cp16(xr_a + (t & 1) * HSB + (i1 >> 5) * RP + (i1 & 31) * 16, s1);
            }
            cp_commit();                             // keep wait accounting

            if (pu == 0) {                           // publish progress
                asm volatile("st.release.cta.shared.u32 [%0], %1;"
                             :: "r"(flag_a), "r"((uint32_t)(t + 1)));
            }
        }
        // producers exit; consumers continue on named barrier 1
    }
}

// ---------------------------------------------------------------------------
// launch
// ---------------------------------------------------------------------------
extern "C" void kernel_launch(void* const* d_in, const int* in_sizes, int n_in,
                              void* d_out, int out_size) {
    const float* input     = (const float*)d_in[0];   // [T, B, H]
    const float* initial_h = (const float*)d_in[1];   // [B, H]
    const float* w_ih      = (const float*)d_in[2];   // [3H, H]
    const float* w_hh      = (const float*)d_in[3];   // [3H, H]
    const float* b_ih      = (const float*)d_in[4];   // [3H]
    const float* b_hh      = (const float*)d_in[5];   // [3H]
    const float* w_out     = (const float*)d_in[6];   // [1, H]
    const float* b_out     = (const float*)d_in[7];   // [1]
    float*       out       = (float*)d_out;           // [B, 1]

    (void)in_sizes; (void)n_in; (void)out_size;

    cudaFuncSetAttribute(fused_gru, cudaFuncAttributeMaxDynamicSharedMemorySize, SMEMF);

    transpose_wih<<<24, 512>>>(w_ih);
    fused_gru<<<BB / 8, THRF, SMEMF>>>(input, initial_h, w_hh, b_ih, b_hh,
                                       w_out, b_out, out);
}

// round 15
// speedup vs baseline: 1.0270x; 1.0270x over previous
#include <cuda_runtime.h>
#include <math.h>
#include <stdint.h>

// ---------------------------------------------------------------------------
// GRU: T=512, B=1024, H=128.  out = h_T @ w_out^T + b_out
//
// FUSED kernel v2: 128 CTAs x 512 threads (4 warps/SMSP).
//   threads 0..255  : CONSUMER — R11 split-K-2 recurrence, w_hh in smem.
//   threads 256..511: PRODUCER — xg[t] = x[t]@w_ih^T + b_ih for this CTA's
//     8 batch rows. 8 warps; lane = (ul 4b | kh 1b): warp covers 16 gate
//     units x 2 k-halves, all 8 rows. Weights streamed from L2 (LDG.128,
//     1x traffic), k-half partials reduced with ONE shfl_xor(16), results
//     STG'd to g_xg, published via fence -> producer-bar -> release flag.
//   Producer free-runs ahead of the consumer; per-SMSP fma demand is
//   6144 cyc/step (2 consumer + 2 producer warps) and producer FFMA2 fills
//   the consumer's stall windows.
// ---------------------------------------------------------------------------

typedef unsigned long long u64;

static __device__ __forceinline__ u64 pack2(float lo, float hi) {
    u64 r; asm("mov.b64 %0, {%1, %2};" : "=l"(r) : "f"(lo), "f"(hi)); return r;
}
static __device__ __forceinline__ void unpack2(u64 v, float& lo, float& hi) {
    asm("mov.b64 {%0, %1}, %2;" : "=f"(lo), "=f"(hi) : "l"(v));
}
static __device__ __forceinline__ u64 ffma2(u64 a, u64 b, u64 c) {
    u64 d; asm("fma.rn.f32x2 %0, %1, %2, %3;" : "=l"(d) : "l"(a), "l"(b), "l"(c)); return d;
}
static __device__ __forceinline__ void lds_v2u64(u64& a, u64& b, uint32_t addr) {
    asm volatile("ld.shared.v2.u64 {%0, %1}, [%2];" : "=l"(a), "=l"(b) : "r"(addr));
}
static __device__ __forceinline__ void ldg_v2u64(u64& a, u64& b, const void* p) {
    asm volatile("ld.global.nc.v2.u64 {%0, %1}, [%2];" : "=l"(a), "=l"(b) : "l"(p));
}
static __device__ __forceinline__ uint32_t smem_u32(const void* p) {
    uint32_t a;
    asm("{ .reg .u64 t; cvta.to.shared.u64 t, %1; cvt.u32.u64 %0, t; }" : "=r"(a) : "l"(p));
    return a;
}
static __device__ __forceinline__ void cp16(uint32_t dst, const void* src) {
    asm volatile("cp.async.cg.shared.global [%0], [%1], 16;" :: "r"(dst), "l"(src));
}
static __device__ __forceinline__ void cp_commit() { asm volatile("cp.async.commit_group;"); }
static __device__ __forceinline__ void cp_wait1()  { asm volatile("cp.async.wait_group 1;"); }
static __device__ __forceinline__ float sigf(float x) {
    return __fdividef(1.0f, 1.0f + __expf(-x));
}
static __device__ __forceinline__ float tanhf_fast(float x) {
    float ax = fabsf(x);
    float e  = __expf(-2.0f * ax);
    float t  = __fdividef(1.0f - e, 1.0f + e);
    return copysignf(t, x);
}

constexpr int H  = 128;
constexpr int G  = 384;    // 3*H
constexpr int TT = 512;
constexpr int BB = 1024;

// xg scratch [T*B][3H] (~805 MB) and transposed w_ih [kk][g] (float4)
__device__ float  g_xg[(size_t)TT * BB * G];
__device__ float4 g_wt[32 * G];

constexpr int WS_BYTES = 32 * G * 16;   // 196608: w_hh as [kk][g] float4
constexpr int RP       = 528;           // row pitch bytes (132 floats)
constexpr int HSB      = 8 * RP;        // 4224: one h (or x) buffer
constexpr int PXSIDE   = 4 * 3 * 128 * 4;   // 6144

constexpr int OFF_HS   = WS_BYTES;               // 196608  (2 x 4224)
constexpr int OFF_CPX  = OFF_HS + 2 * HSB;       // 205056  (2 x 6144)
constexpr int OFF_XR   = OFF_CPX + 2 * PXSIDE;   // 217344  (2 x 4224)
constexpr int OFF_RED  = OFF_XR;                 // alias: used only after producers exit
constexpr int OFF_FLAG = OFF_XR + 2 * HSB;       // 225792
constexpr int SMEMF    = OFF_FLAG + 64;          // 225856

constexpr int THRF = 512;

// ---------------------------------------------------------------------------
// tiny pre-kernel: transpose w_ih into [kk][g] float4 layout in global
// ---------------------------------------------------------------------------
__global__ void transpose_wih(const float* __restrict__ w_ih) {
    int i = blockIdx.x * blockDim.x + threadIdx.x;   // 0..12287
    if (i < G * 32) {
        int g = i >> 5, kk = i & 31;
        g_wt[kk * G + g] = ((const float4*)w_ih)[g * 32 + kk];
    }
}

// ---------------------------------------------------------------------------
// fused kernel
// ---------------------------------------------------------------------------
__global__ void __launch_bounds__(THRF, 1)
fused_gru(const float* __restrict__ input,
          const float* __restrict__ initial_h,
          const float* __restrict__ w_hh,
          const float* __restrict__ b_ih,
          const float* __restrict__ b_hh,
          const float* __restrict__ w_out,
          const float* __restrict__ b_out,
          float* __restrict__ out) {
    extern __shared__ char smem[];
    float4* ws4 = (float4*)smem;
    float*  hsf = (float*)(smem + OFF_HS);
    float*  pxf = (float*)(smem + OFF_CPX);
    float*  red = (float*)(smem + OFF_RED);
    const uint32_t ws_a   = smem_u32(smem);
    const uint32_t hs_a   = ws_a + OFF_HS;
    const uint32_t xr_a   = ws_a + OFF_XR;
    const uint32_t flag_a = ws_a + OFF_FLAG;

    const int tid = threadIdx.x;
    const int b0  = blockIdx.x * 8;

    // ---- shared init (all 512 threads): w_hh -> smem, flag = 0 ----
    const float4* w4 = (const float4*)w_hh;
    for (int i = tid; i < G * 32; i += THRF) {
        int g = i >> 5, kk = i & 31;
        ws4[kk * G + g] = w4[g * 32 + kk];
    }
    if (tid == 0) {
        asm volatile("st.shared.u32 [%0], %1;" :: "r"(flag_a), "r"(0u));
    }
    __syncthreads();   // the ONLY full-CTA barrier

    if (tid < 256) {
        // =================== CONSUMER (R11 recurrence) ===================
        const int u  = tid & 127;
        const int kh = tid >> 7;
        const int r0 = kh * 4;
        const int ro = 4 - r0;

        const float br = b_hh[u], bz = b_hh[u + 128], bn = b_hh[u + 256];

        float hreg[4];
        #pragma unroll
        for (int i = 0; i < 4; i++) {
            hreg[i] = initial_h[(size_t)(b0 + r0 + i) * H + u];
            hsf[(r0 + i) * 132 + u] = hreg[i];
        }
        asm volatile("bar.sync 1, 256;");   // h staged (consumer-only barrier)

        // wait for xg[0], then prefetch it
        {
            uint32_t fv;
            do { asm volatile("ld.acquire.cta.shared.u32 %0, [%1];" : "=r"(fv) : "r"(flag_a)); }
            while ((int)fv < 1);
        }
        float cxR[4], cxZ[4], cxN[4];
        {
            const float* xg0 = g_xg + ((size_t)b0 + r0) * G + u;
            #pragma unroll
            for (int i = 0; i < 4; i++) {
                cxR[i] = xg0[(size_t)i * G];
                cxZ[i] = xg0[(size_t)i * G + 128];
                cxN[i] = xg0[(size_t)i * G + 256];
            }
        }

        const uint32_t wb  = ws_a + u * 16 + kh * 16 * (G * 16);
        float* pxw = pxf + kh * (4 * 3 * 128) + u;
        float* pxr = pxf + (1 - kh) * (4 * 3 * 128) + u;

        int p = 0;
        for (int t = 0; t < TT; t++) {
            // wait until xg[t+1] is published, then prefetch it
            {
                int need = (t + 2 < TT) ? (t + 2) : TT;
                uint32_t fv;
                do { asm volatile("ld.acquire.cta.shared.u32 %0, [%1];" : "=r"(fv) : "r"(flag_a)); }
                while ((int)fv < need);
            }
            float nxR[4], nxZ[4], nxN[4];
            {
                int tn = (t + 1 < TT) ? (t + 1) : t;
                const float* xgn = g_xg + ((size_t)tn * BB + b0 + r0) * G + u;
                #pragma unroll
                for (int i = 0; i < 4; i++) {
                    nxR[i] = xgn[(size_t)i * G];
                    nxZ[i] = xgn[(size_t)i * G + 128];
                    nxN[i] = xgn[(size_t)i * G + 256];
                }
            }

            // accumulators: [0..3] own rows (x folded), [4..7] other rows
            u64 aR[8], aZ[8], aN[8];
            #pragma unroll
            for (int i = 0; i < 4; i++) {
                aR[i] = pack2(cxR[i] + br, 0.f);
                aZ[i] = pack2(cxZ[i] + bz, 0.f);
                aN[i] = pack2(bn, 0.f);
                aR[4 + i] = 0; aZ[4 + i] = 0; aN[4 + i] = 0;
            }

            const uint32_t hb_own = hs_a + p * HSB + r0 * RP + kh * 256;
            const uint32_t hb_oth = hs_a + p * HSB + ro * RP + kh * 256;

            #pragma unroll 2
            for (int kk = 0; kk < 16; kk++) {
                u64 wr0, wr1, wz0, wz1, wn0, wn1;
                const uint32_t wo = wb + kk * (G * 16);
                lds_v2u64(wr0, wr1, wo);
                lds_v2u64(wz0, wz1, wo + 128 * 16);
                lds_v2u64(wn0, wn1, wo + 256 * 16);
                #pragma unroll
                for (int i = 0; i < 4; i++) {
                    u64 x0, x1;
                    lds_v2u64(x0, x1, hb_own + i * RP + kk * 16);
                    aR[i] = ffma2(x0, wr0, aR[i]); aR[i] = ffma2(x1, wr1, aR[i]);
                    aZ[i] = ffma2(x0, wz0, aZ[i]); aZ[i] = ffma2(x1, wz1, aZ[i]);
                    aN[i] = ffma2(x0, wn0, aN[i]); aN[i] = ffma2(x1, wn1, aN[i]);
                }
                #pragma unroll
                for (int i = 0; i < 4; i++) {
                    u64 x0, x1;
                    lds_v2u64(x0, x1, hb_oth + i * RP + kk * 16);
                    aR[4+i] = ffma2(x0, wr0, aR[4+i]); aR[4+i] = ffma2(x1, wr1, aR[4+i]);
                    aZ[4+i] = ffma2(x0, wz0, aZ[4+i]); aZ[4+i] = ffma2(x1, wz1, aZ[4+i]);
                    aN[4+i] = ffma2(x0, wn0, aN[4+i]); aN[4+i] = ffma2(x1, wn1, aN[4+i]);
                }
            }

            // fold own sums; export other-rows partials
            float sR[4], sZ[4], sN[4];
            #pragma unroll
            for (int i = 0; i < 4; i++) {
                float l, h2;
                unpack2(aR[i], l, h2); sR[i] = l + h2;
                unpack2(aZ[i], l, h2); sZ[i] = l + h2;
                unpack2(aN[i], l, h2); sN[i] = l + h2;
                unpack2(aR[4+i], l, h2); pxw[i * 384 + 0  ] = l + h2;
                unpack2(aZ[4+i], l, h2); pxw[i * 384 + 128] = l + h2;
                unpack2(aN[4+i], l, h2); pxw[i * 384 + 256] = l + h2;
            }
            asm volatile("bar.sync 1, 256;");   // partials exchanged; hs[p] reads done

            float* hw = hsf + (p ^ 1) * (HSB / 4) + r0 * 132 + u;
            #pragma unroll
            for (int i = 0; i < 4; i++) {
                float rg = sigf(sR[i] + pxr[i * 384 + 0]);
                float zg = sigf(sZ[i] + pxr[i * 384 + 128]);
                float ng = tanhf_fast(cxN[i] + rg * (sN[i] + pxr[i * 384 + 256]));
                hreg[i] = (1.0f - zg) * ng + zg * hreg[i];
                hw[i * 132] = hreg[i];
                cxR[i] = nxR[i]; cxZ[i] = nxZ[i]; cxN[i] = nxN[i];
            }
            asm volatile("bar.sync 1, 256;");   // new h visible
            p ^= 1;
        }

        // projection: out[b] = sum_u h[b][u]*w_out[u] + b_out
        // red aliases the producer x-staging area (producers have exited).
        const float wo = w_out[u];
        #pragma unroll
        for (int i = 0; i < 4; i++) red[(r0 + i) * H + u] = hreg[i] * wo;
        asm volatile("bar.sync 1, 256;");
        for (int st = 64; st > 0; st >>= 1) {
            if (u < st) {
                #pragma unroll
                for (int i = 0; i < 4; i++)
                    red[(r0 + i) * H + u] += red[(r0 + i) * H + u + st];
            }
            asm volatile("bar.sync 1, 256;");
        }
        if (tid < 8) out[b0 + tid] = red[tid * H] + b_out[0];

    } else {
        // =================== PRODUCER (input GEMM, free-running) ===========
        const int pu   = tid - 256;          // 0..255
        const int lane = pu & 31;
        const int pwrp = pu >> 5;            // 0..7
        const int ul   = lane & 15;
        const int kh   = lane >> 4;          // k-half
        const int u    = pwrp * 16 + ul;     // 0..127
        const int rb   = kh * 4;             // STG rows: rb..rb+3

        const float bir = (kh == 0) ? b_ih[u]       : 0.f;
        const float biz = (kh == 0) ? b_ih[u + 128] : 0.f;
        const float bin = (kh == 0) ? b_ih[u + 256] : 0.f;

        // pre-stage x[0], x[1]: 256 threads x 16B = one 8x128 tile each
        const uint32_t xdst = xr_a + (pu >> 5) * RP + (pu & 31) * 16;
        #pragma unroll
        for (int tt = 0; tt < 2; tt++) {
            const float* src = input + (((size_t)tt * BB + b0 + (pu >> 5)) * H + (pu & 31) * 4);
            cp16(xdst + tt * HSB, src);
            cp_commit();
        }

        for (int t = 0; t < TT; t++) {
            cp_wait1();                              // x[t] staged
            asm volatile("bar.sync 2, 256;");        // visible to all producers

            const uint32_t xb = xr_a + (t & 1) * HSB + kh * 256;

            u64 aR[8], aZ[8], aN[8];
            #pragma unroll
            for (int r = 0; r < 8; r++) {
                aR[r] = pack2(bir, 0.f); aZ[r] = pack2(biz, 0.f); aN[r] = pack2(bin, 0.f);
            }

            #pragma unroll 4
            for (int kk = 0; kk < 16; kk++) {
                const int kkg = kh * 16 + kk;
                u64 wr0, wr1, wz0, wz1, wn0, wn1;
                const float4* wp = g_wt + kkg * G;
                ldg_v2u64(wr0, wr1, wp + u);         // L2-hot, 1x traffic
                ldg_v2u64(wz0, wz1, wp + u + 128);
                ldg_v2u64(wn0, wn1, wp + u + 256);
                #pragma unroll
                for (int row = 0; row < 8; row++) {
                    u64 x0, x1;
                    lds_v2u64(x0, x1, xb + row * RP + kk * 16);   // 2x16B bcast
                    aR[row] = ffma2(x0, wr0, aR[row]); aR[row] = ffma2(x1, wr1, aR[row]);
                    aZ[row] = ffma2(x0, wz0, aZ[row]); aZ[row] = ffma2(x1, wz1, aZ[row]);
                    aN[row] = ffma2(x0, wn0, aN[row]); aN[row] = ffma2(x1, wn1, aN[row]);
                }
            }

            // fold + reduce across k-halves (partner lane = lane ^ 16)
            float sv[24];
            #pragma unroll
            for (int row = 0; row < 8; row++) {
                float l, h2;
                unpack2(aR[row], l, h2); sv[row * 3 + 0] = l + h2;
                unpack2(aZ[row], l, h2); sv[row * 3 + 1] = l + h2;
                unpack2(aN[row], l, h2); sv[row * 3 + 2] = l + h2;
            }
            #pragma unroll
            for (int v = 0; v < 24; v++)
                sv[v] += __shfl_xor_sync(0xffffffffu, sv[v], 16);

            // each k-half lane writes 4 distinct rows (16-lane coalesced, 64B)
            float* outp = g_xg + ((size_t)t * BB + b0 + rb) * G + u;
            #pragma unroll
            for (int i = 0; i < 4; i++) {
                int row = rb + i;
                outp[(size_t)i * G]       = sv[row * 3 + 0];
                outp[(size_t)i * G + 128] = sv[row * 3 + 1];
                outp[(size_t)i * G + 256] = sv[row * 3 + 2];
            }

            __threadfence_block();                   // STGs visible CTA-wide
            asm volatile("bar.sync 2, 256;");        // all STGs + x[t] reads done

            int tn = t + 2;
            if (tn < TT) {                           // refill buffer (t&1) with x[t+2]
                const float* src = input + (((size_t)tn * BB + b0 + (pu >> 5)) * H + (pu & 31) * 4);
                cp16(xdst + (t & 1) * HSB, src);
            }
            cp_commit();                             // keep wait accounting

            if (pu == 0) {                           // publish progress
                asm volatile("st.release.cta.shared.u32 [%0], %1;"
                             :: "r"(flag_a), "r"((uint32_t)(t + 1)));
            }
        }
        // producers exit; consumers continue on named barrier 1
    }
}

// ---------------------------------------------------------------------------
// launch
// ---------------------------------------------------------------------------
extern "C" void kernel_launch(void* const* d_in, const int* in_sizes, int n_in,
                              void* d_out, int out_size) {
    const float* input     = (const float*)d_in[0];   // [T, B, H]
    const float* initial_h = (const float*)d_in[1];   // [B, H]
    const float* w_ih      = (const float*)d_in[2];   // [3H, H]
    const float* w_hh      = (const float*)d_in[3];   // [3H, H]
    const float* b_ih      = (const float*)d_in[4];   // [3H]
    const float* b_hh      = (const float*)d_in[5];   // [3H]
    const float* w_out     = (const float*)d_in[6];   // [1, H]
    const float* b_out     = (const float*)d_in[7];   // [1]
    float*       out       = (float*)d_out;           // [B, 1]

    (void)in_sizes; (void)n_in; (void)out_size;

    cudaFuncSetAttribute(fused_gru, cudaFuncAttributeMaxDynamicSharedMemorySize, SMEMF);

    transpose_wih<<<24, 512>>>(w_ih);
    fused_gru<<<BB / 8, THRF, SMEMF>>>(input, initial_h, w_hh, b_ih, b_hh,
                                       w_out, b_out, out);
}

// round 17
// speedup vs baseline: 1.4415x; 1.4037x over previous
#include <cuda_runtime.h>
#include <cuda_bf16.h>
#include <math.h>
#include <stdint.h>

// ---------------------------------------------------------------------------
// GRU: T=512, B=1024, H=128.  out = h_T @ w_out^T + b_out
//
// Phase 1 (xg_kernel): persistent FFMA2 GEMM (proven R11/R12 version).
// Phase 2 (gru_mma):   recurrence on mma.sync.m16n8k16 (bf16 in, f32 acc)
//   — baseline PTX, compiles for compute_103 (tcgen05 does NOT in this env).
//   Per CTA (8 batch rows): D[384x8] = w_hh @ h^T, M=24 m16-tiles, N=8
//   (exactly the batch rows), K=8 k16-tiles. bf16 hi/lo split:
//     D = Ahi.Bhi + Ahi.Blo + Alo.Bhi   (72 mma/warp/step, 8 warps).
//   A (w_hh hi/lo) staged once in smem (pitch 272B -> conflict-free LDSM);
//   B (h) restaged per step by gate threads as bf16 hi/lo; D exchanged via
//   smem (pitch 36B -> conflict-free gate reads). Two barriers per step.
// ---------------------------------------------------------------------------

typedef unsigned long long u64;

static __device__ __forceinline__ u64 pack2(float lo, float hi) {
    u64 r; asm("mov.b64 %0, {%1, %2};" : "=l"(r) : "f"(lo), "f"(hi)); return r;
}
static __device__ __forceinline__ void unpack2(u64 v, float& lo, float& hi) {
    asm("mov.b64 {%0, %1}, %2;" : "=f"(lo), "=f"(hi) : "l"(v));
}
static __device__ __forceinline__ u64 ffma2(u64 a, u64 b, u64 c) {
    u64 d; asm("fma.rn.f32x2 %0, %1, %2, %3;" : "=l"(d) : "l"(a), "l"(b), "l"(c)); return d;
}
static __device__ __forceinline__ void lds_v2u64(u64& a, u64& b, uint32_t addr) {
    asm volatile("ld.shared.v2.u64 {%0, %1}, [%2];" : "=l"(a), "=l"(b) : "r"(addr));
}
static __device__ __forceinline__ uint32_t smem_u32(const void* p) {
    uint32_t a;
    asm("{ .reg .u64 t; cvta.to.shared.u64 t, %1; cvt.u32.u64 %0, t; }" : "=r"(a) : "l"(p));
    return a;
}
static __device__ __forceinline__ void cp16(uint32_t dst, const void* src) {
    asm volatile("cp.async.cg.shared.global [%0], [%1], 16;" :: "r"(dst), "l"(src));
}
static __device__ __forceinline__ void cp_commit() { asm volatile("cp.async.commit_group;"); }
static __device__ __forceinline__ void cp_wait1()  { asm volatile("cp.async.wait_group 1;"); }
static __device__ __forceinline__ void cp_wait0()  { asm volatile("cp.async.wait_group 0;"); }
static __device__ __forceinline__ float sigf(float x) {
    return __fdividef(1.0f, 1.0f + __expf(-x));
}
static __device__ __forceinline__ float tanhf_fast(float x) {
    float ax = fabsf(x);
    float e  = __expf(-2.0f * ax);
    float t  = __fdividef(1.0f - e, 1.0f + e);
    return copysignf(t, x);
}

constexpr int H  = 128;
constexpr int G  = 384;    // 3*H
constexpr int TT = 512;
constexpr int BB = 1024;

// precomputed input gates: [T*B][3H]  (~805 MB static device scratch)
__device__ float g_xg[(size_t)TT * BB * G];

constexpr int WS_BYTES = 32 * G * 16;      // 196608
constexpr int RP       = 528;              // x row pitch bytes (132 floats)

// ---------------------------------------------------------------------------
// Phase 1: g_xg = input @ w_ih^T + b_ih   (persistent GEMM, cp.async staging)
// ---------------------------------------------------------------------------
constexpr int ROWS1    = 32;
constexpr int THR1     = 512;
constexpr int NBLK1    = (TT * BB) / ROWS1;   // 16384 tiles
constexpr int GRID1    = 148;
constexpr int XS_BYTES = ROWS1 * RP;          // 16896
constexpr int SMEM1    = WS_BYTES + 2 * XS_BYTES;   // 230400

__global__ void __launch_bounds__(THR1) xg_kernel(const float* __restrict__ input,
                                                  const float* __restrict__ w_ih,
                                                  const float* __restrict__ b_ih) {
    extern __shared__ char smem[];
    float4* ws4 = (float4*)smem;
    const uint32_t ws_a = smem_u32(smem);
    const uint32_t xs_a = ws_a + WS_BYTES;

    const int tid  = threadIdx.x;
    const int lane = tid & 31;
    const int wrp  = tid >> 5;
    const int ul   = lane & 7;
    const int rl   = lane >> 3;        // 0..3
    const int u    = wrp * 8 + ul;     // 0..127

    const int i0 = tid, i1 = tid + THR1;
    const uint32_t d0 = xs_a + (i0 >> 5) * RP + (i0 & 31) * 16;
    const uint32_t d1 = xs_a + (i1 >> 5) * RP + (i1 & 31) * 16;
    {
        const float4* in4 = (const float4*)(input + (size_t)blockIdx.x * ROWS1 * H);
        cp16(d0, in4 + i0); cp16(d1, in4 + i1); cp_commit();
        const float4* in4b = (const float4*)(input + (size_t)(blockIdx.x + GRID1) * ROWS1 * H);
        cp16(d0 + XS_BYTES, in4b + i0); cp16(d1 + XS_BYTES, in4b + i1); cp_commit();
    }

    const float4* w4 = (const float4*)w_ih;
    for (int i = tid; i < G * 32; i += THR1) {
        int g = i >> 5, kk = i & 31;
        ws4[kk * G + g] = w4[g * 32 + kk];
    }
    const float br = b_ih[u], bz = b_ih[u + 128], bn = b_ih[u + 256];

    const uint32_t wb = ws_a + u * 16;
    int p = 0;

    for (int j = blockIdx.x; j < NBLK1; j += GRID1) {
        cp_wait1();
        __syncthreads();

        const uint32_t xb = xs_a + p * XS_BYTES + rl * RP;

        u64 aR[8], aZ[8], aN[8];
        #pragma unroll
        for (int r = 0; r < 8; r++) {
            aR[r] = pack2(br, 0.f); aZ[r] = pack2(bz, 0.f); aN[r] = pack2(bn, 0.f);
        }

        #pragma unroll 4
        for (int kk = 0; kk < 32; kk++) {
            u64 wr0, wr1, wz0, wz1, wn0, wn1;
            const uint32_t wo = wb + kk * (G * 16);
            lds_v2u64(wr0, wr1, wo);
            lds_v2u64(wz0, wz1, wo + 128 * 16);
            lds_v2u64(wn0, wn1, wo + 256 * 16);
            #pragma unroll
            for (int jj = 0; jj < 8; jj++) {
                u64 x0, x1;
                lds_v2u64(x0, x1, xb + jj * (4 * RP) + kk * 16);
                aR[jj] = ffma2(x0, wr0, aR[jj]); aR[jj] = ffma2(x1, wr1, aR[jj]);
                aZ[jj] = ffma2(x0, wz0, aZ[jj]); aZ[jj] = ffma2(x1, wz1, aZ[jj]);
                aN[jj] = ffma2(x0, wn0, aN[jj]); aN[jj] = ffma2(x1, wn1, aN[jj]);
            }
        }

        float* outp = g_xg + ((size_t)j * ROWS1 + rl) * G + u;
        #pragma unroll
        for (int jj = 0; jj < 8; jj++) {
            float l, h2;
            size_t ro = (size_t)(4 * jj) * G;
            unpack2(aR[jj], l, h2); outp[ro]       = l + h2;
            unpack2(aZ[jj], l, h2); outp[ro + 128] = l + h2;
            unpack2(aN[jj], l, h2); outp[ro + 256] = l + h2;
        }

        __syncthreads();
        int jn = j + 2 * GRID1;
        if (jn < NBLK1) {
            const float4* in4 = (const float4*)(input + (size_t)jn * ROWS1 * H);
            cp16(xs_a + p * XS_BYTES + (i0 >> 5) * RP + (i0 & 31) * 16, in4 + i0);
            cp16(xs_a + p * XS_BYTES + (i1 >> 5) * RP + (i1 & 31) * 16, in4 + i1);
        }
        cp_commit();
        p ^= 1;
    }
    cp_wait0();
}

// ---------------------------------------------------------------------------
// Phase 2: mma.sync recurrence. 128 CTAs x 256 threads (8 warps).
// ---------------------------------------------------------------------------
static __device__ __forceinline__ void ldsm4(uint32_t r[4], uint32_t addr) {
    asm volatile("ldmatrix.sync.aligned.m8n8.x4.shared.b16 {%0,%1,%2,%3}, [%4];"
        : "=r"(r[0]), "=r"(r[1]), "=r"(r[2]), "=r"(r[3]) : "r"(addr));
}
static __device__ __forceinline__ void mma16816(float c[4], const uint32_t a[4],
                                                uint32_t b0, uint32_t b1) {
    asm volatile(
        "mma.sync.aligned.m16n8k16.row.col.f32.bf16.bf16.f32 "
        "{%0,%1,%2,%3}, {%4,%5,%6,%7}, {%8,%9}, {%0,%1,%2,%3};"
        : "+f"(c[0]), "+f"(c[1]), "+f"(c[2]), "+f"(c[3])
        : "r"(a[0]), "r"(a[1]), "r"(a[2]), "r"(a[3]), "r"(b0), "r"(b1));
}
static __device__ __forceinline__ uint32_t lds_u32(uint32_t addr) {
    uint32_t v; asm volatile("ld.shared.b32 %0, [%1];" : "=r"(v) : "r"(addr)); return v;
}
static __device__ __forceinline__ float lds_f32(uint32_t addr) {
    float v; asm volatile("ld.shared.f32 %0, [%1];" : "=f"(v) : "r"(addr)); return v;
}
static __device__ __forceinline__ void sts_f32(uint32_t addr, float v) {
    asm volatile("st.shared.f32 [%0], %1;" :: "r"(addr), "f"(v));
}
static __device__ __forceinline__ void sts_b16(uint32_t addr, unsigned short v) {
    asm volatile("st.shared.b16 [%0], %1;" :: "r"(addr), "h"(v));
}
static __device__ __forceinline__ unsigned short bf16b(float x) {
    return __bfloat16_as_ushort(__float2bfloat16(x));
}

constexpr int AP      = 272;                    // A row pitch (17 x 16B)
constexpr int OFF_AHI = 0;                      // 384*272 = 104448
constexpr int OFF_ALO = 104448;                 // 104448
constexpr int OFF_BHI = 208896;                 // 8*272 = 2176
constexpr int OFF_BLO = 211072;                 // 2176
constexpr int OFF_D   = 213248;                 // 384*36 = 13824 -> 227072
constexpr int OFF_RED = OFF_D;                  // alias (projection epilogue)
constexpr int SMEM2   = 227072;
constexpr int THR2    = 256;

__global__ void __launch_bounds__(THR2, 1)
gru_mma(const float* __restrict__ initial_h,
        const float* __restrict__ w_hh,
        const float* __restrict__ b_hh,
        const float* __restrict__ w_out,
        const float* __restrict__ b_out,
        float* __restrict__ out) {
    extern __shared__ char smem[];
    const uint32_t sb = smem_u32(smem);
    const int tid  = threadIdx.x;
    const int lane = tid & 31;
    const int wrp  = tid >> 5;           // 0..7
    const int b0   = blockIdx.x * 8;

    // gate-phase identity: unit u, row-half rh (rows rh*4 .. rh*4+3)
    const int u  = tid & 127;
    const int rh = tid >> 7;

    // ---- stage A = w_hh as bf16 hi/lo, row-major pitch 272 ----
    for (int i = tid; i < G * H; i += THR2) {
        int row = i >> 7, col = i & 127;
        float w = w_hh[(size_t)i];
        unsigned short hi = bf16b(w);
        float rem = w - __bfloat162float(__ushort_as_bfloat16(hi));
        uint32_t a = sb + row * AP + col * 2;
        sts_b16(a + OFF_AHI, hi);
        sts_b16(a + OFF_ALO, bf16b(rem));
    }

    // ---- init h (regs) + stage B = h bf16 hi/lo [row][k], pitch 272 ----
    float hreg[4];
    #pragma unroll
    for (int i = 0; i < 4; i++) {
        int r = rh * 4 + i;
        float v = initial_h[(size_t)(b0 + r) * H + u];
        hreg[i] = v;
        unsigned short hi = bf16b(v);
        float rem = v - __bfloat162float(__ushort_as_bfloat16(hi));
        sts_b16(sb + OFF_BHI + r * AP + u * 2, hi);
        sts_b16(sb + OFF_BLO + r * AP + u * 2, bf16b(rem));
    }

    const float br = b_hh[u], bz = b_hh[u + 128], bn = b_hh[u + 256];
    const float wo = w_out[u];

    // prefetch xg[0] for own 4 rows
    float cx[12];
    {
        const float* xg = g_xg + ((size_t)b0 + rh * 4) * G + u;
        #pragma unroll
        for (int i = 0; i < 4; i++) {
            cx[i * 3 + 0] = xg[(size_t)i * G];
            cx[i * 3 + 1] = xg[(size_t)i * G + 128];
            cx[i * 3 + 2] = xg[(size_t)i * G + 256];
        }
    }
    __syncthreads();

    // mma-phase lane decode
    const int fg = lane >> 2;            // fragment group 0..7 (batch row / D row)
    const int ft = lane & 3;             // fragment thread 0..3
    // ldmatrix lane address components (A, 16x16 tiles)
    const int arow = lane & 15;          // row within m16 tile
    const int acol = (lane >> 4) * 16;   // 0 or +16 bytes (k half)

    for (int t = 0; t < TT; t++) {
        // prefetch next step's xg (own rows)
        float nx[12];
        {
            int tn = (t + 1 < TT) ? (t + 1) : t;
            const float* xg = g_xg + ((size_t)tn * BB + b0 + rh * 4) * G + u;
            #pragma unroll
            for (int i = 0; i < 4; i++) {
                nx[i * 3 + 0] = xg[(size_t)i * G];
                nx[i * 3 + 1] = xg[(size_t)i * G + 128];
                nx[i * 3 + 2] = xg[(size_t)i * G + 256];
            }
        }

        // ---- MMA phase: warp wrp computes D rows [wrp*48, wrp*48+48) ----
        // preload B fragments for all 8 k-tiles (hi and lo)
        uint32_t bh[16], bl[16];
        #pragma unroll
        for (int kt = 0; kt < 8; kt++) {
            uint32_t ba = sb + fg * AP + kt * 32 + ft * 4;
            bh[kt * 2]     = lds_u32(ba + OFF_BHI);
            bh[kt * 2 + 1] = lds_u32(ba + OFF_BHI + 16);
            bl[kt * 2]     = lds_u32(ba + OFF_BLO);
            bl[kt * 2 + 1] = lds_u32(ba + OFF_BLO + 16);
        }

        #pragma unroll
        for (int m = 0; m < 3; m++) {
            const int mrow = (wrp * 3 + m) * 16;
            float c[4] = {0.f, 0.f, 0.f, 0.f};
            const uint32_t abase = sb + (mrow + arow) * AP + acol;
            #pragma unroll
            for (int kt = 0; kt < 8; kt++) {
                uint32_t ahi[4], alo[4];
                ldsm4(ahi, abase + OFF_AHI + kt * 32);
                ldsm4(alo, abase + OFF_ALO + kt * 32);
                mma16816(c, ahi, bh[kt * 2], bh[kt * 2 + 1]);
                mma16816(c, ahi, bl[kt * 2], bl[kt * 2 + 1]);
                mma16816(c, alo, bh[kt * 2], bh[kt * 2 + 1]);
            }
            // D[gate][batchrow], pitch 36B: c0=D[g][2t], c1=D[g][2t+1],
            // c2=D[g+8][2t], c3=D[g+8][2t+1]
            uint32_t dbase = sb + OFF_D + (mrow + fg) * 36 + ft * 8;
            sts_f32(dbase,           c[0]);
            sts_f32(dbase + 4,       c[1]);
            sts_f32(dbase + 8 * 36,  c[2]);
            sts_f32(dbase + 8 * 36 + 4, c[3]);
        }
        __syncthreads();   // D ready; all B reads done

        // ---- gate phase: thread (u, rh) finalizes rows rh*4..rh*4+3 ----
        #pragma unroll
        for (int i = 0; i < 4; i++) {
            int r = rh * 4 + i;
            float hr = lds_f32(sb + OFF_D + u * 36 + r * 4);
            float hz = lds_f32(sb + OFF_D + (u + 128) * 36 + r * 4);
            float hn = lds_f32(sb + OFF_D + (u + 256) * 36 + r * 4);
            float rg = sigf(cx[i * 3 + 0] + hr + br);
            float zg = sigf(cx[i * 3 + 1] + hz + bz);
            float ng = tanhf_fast(cx[i * 3 + 2] + rg * (hn + bn));
            hreg[i] = (1.0f - zg) * ng + zg * hreg[i];
            unsigned short hi = bf16b(hreg[i]);
            float rem = hreg[i] - __bfloat162float(__ushort_as_bfloat16(hi));
            sts_b16(sb + OFF_BHI + r * AP + u * 2, hi);
            sts_b16(sb + OFF_BLO + r * AP + u * 2, bf16b(rem));
            cx[i * 3 + 0] = nx[i * 3 + 0];
            cx[i * 3 + 1] = nx[i * 3 + 1];
            cx[i * 3 + 2] = nx[i * 3 + 2];
        }
        __syncthreads();   // new h visible; D reads done
    }

    // projection: out[b] = sum_u h[b][u]*w_out[u] + b_out (deterministic tree)
    float* red = (float*)(smem + OFF_RED);
    #pragma unroll
    for (int i = 0; i < 4; i++) red[(rh * 4 + i) * H + u] = hreg[i] * wo;
    __syncthreads();
    for (int st = 64; st > 0; st >>= 1) {
        if (u < st) {
            #pragma unroll
            for (int i = 0; i < 4; i++)
                red[(rh * 4 + i) * H + u] += red[(rh * 4 + i) * H + u + st];
        }
        __syncthreads();
    }
    if (tid < 8) out[b0 + tid] = red[tid * H] + b_out[0];
}

// ---------------------------------------------------------------------------
// launch
// ---------------------------------------------------------------------------
extern "C" void kernel_launch(void* const* d_in, const int* in_sizes, int n_in,
                              void* d_out, int out_size) {
    const float* input     = (const float*)d_in[0];   // [T, B, H]
    const float* initial_h = (const float*)d_in[1];   // [B, H]
    const float* w_ih      = (const float*)d_in[2];   // [3H, H]
    const float* w_hh      = (const float*)d_in[3];   // [3H, H]
    const float* b_ih      = (const float*)d_in[4];   // [3H]
    const float* b_hh      = (const float*)d_in[5];   // [3H]
    const float* w_out     = (const float*)d_in[6];   // [1, H]
    const float* b_out     = (const float*)d_in[7];   // [1]
    float*       out       = (float*)d_out;           // [B, 1]

    (void)in_sizes; (void)n_in; (void)out_size;

    cudaFuncSetAttribute(xg_kernel, cudaFuncAttributeMaxDynamicSharedMemorySize, SMEM1);
    cudaFuncSetAttribute(gru_mma,   cudaFuncAttributeMaxDynamicSharedMemorySize, SMEM2);

    xg_kernel<<<GRID1, THR1, SMEM1>>>(input, w_ih, b_ih);
    gru_mma<<<BB / 8, THR2, SMEM2>>>(initial_h, w_hh, b_hh, w_out, b_out, out);
}